// round 14
// baseline (speedup 1.0000x reference)
#include <cuda_runtime.h>
#include <cuda_bf16.h>
#include <math.h>
#include <stdint.h>

#define BSZ 8
#define TSEQ 1024
#define DM 512
#define HN 8
#define HDIM 64
#define LNUM 4
#define FFD 2048
#define NCLS 10
#define NTOK (BSZ * TSEQ)

// ---------------- scratch ----------------------------------------------------
__device__ float g_x [NTOK * DM];
__device__ float g_t [NTOK * DM];
__device__ float g_pool[BSZ * DM];
__device__ float g_bqkv[LNUM * 3 * DM];
__device__ __nv_bfloat16 g_hh [NTOK * DM];
__device__ __nv_bfloat16 g_xh [NTOK * DM];
__device__ __nv_bfloat16 g_qkvh[NTOK * 3 * DM], g_qkvl[NTOK * 3 * DM];
__device__ __nv_bfloat16 g_ath[NTOK * DM];
__device__ __nv_bfloat16 g_ffh[NTOK * FFD];

#define LSTRIDE (3 * DM * DM + DM * DM + DM * FFD + FFD * DM)
#define WT_TOT  (LNUM * LSTRIDE + 3 * DM * DM)
__device__ __nv_bfloat16 g_wt_hi[WT_TOT];
__device__ __nv_bfloat16 g_wt_lo[WT_TOT];
#define OFF_WO (3 * DM * DM)
#define OFF_W1 (OFF_WO + DM * DM)
#define OFF_W2 (OFF_W1 + DM * FFD)

// ---------------- helpers ----------------------------------------------------
__device__ __forceinline__ uint32_t smem_u32(const void* p) {
    uint32_t a;
    asm("{ .reg .u64 t; cvta.to.shared.u64 t, %1; cvt.u32.u64 %0, t; }" : "=r"(a) : "l"(p));
    return a;
}
__device__ __forceinline__ void ldm_x4(uint32_t* r, uint32_t addr) {
    asm volatile("ldmatrix.sync.aligned.m8n8.x4.shared.b16 {%0,%1,%2,%3}, [%4];"
                 : "=r"(r[0]), "=r"(r[1]), "=r"(r[2]), "=r"(r[3]) : "r"(addr));
}
__device__ __forceinline__ void ldm_x4t(uint32_t* r, uint32_t addr) {
    asm volatile("ldmatrix.sync.aligned.m8n8.x4.trans.shared.b16 {%0,%1,%2,%3}, [%4];"
                 : "=r"(r[0]), "=r"(r[1]), "=r"(r[2]), "=r"(r[3]) : "r"(addr));
}
__device__ __forceinline__ void mma_bf16(float* d, const uint32_t* a, const uint32_t* b) {
    asm volatile("mma.sync.aligned.m16n8k16.row.col.f32.bf16.bf16.f32 "
                 "{%0,%1,%2,%3}, {%4,%5,%6,%7}, {%8,%9}, {%0,%1,%2,%3};"
                 : "+f"(d[0]), "+f"(d[1]), "+f"(d[2]), "+f"(d[3])
                 : "r"(a[0]), "r"(a[1]), "r"(a[2]), "r"(a[3]), "r"(b[0]), "r"(b[1]));
}
__device__ __forceinline__ void cp16(uint32_t dst, const void* src) {
    asm volatile("cp.async.cg.shared.global [%0], [%1], 16;" :: "r"(dst), "l"(src));
}
#define CP_COMMIT() asm volatile("cp.async.commit_group;" ::: "memory")
#define CP_WAIT1()  asm volatile("cp.async.wait_group 1;" ::: "memory")
#define CP_WAIT0()  asm volatile("cp.async.wait_group 0;" ::: "memory")

__device__ __forceinline__ uint32_t pack2bf(float lo, float hi) {
    uint32_t r;
    asm("cvt.rn.bf16x2.f32 %0, %1, %2;" : "=r"(r) : "f"(hi), "f"(lo));
    return r;
}
__device__ __forceinline__ void store_hi2(__nv_bfloat16* H, size_t idx, float v0, float v1) {
    *(uint32_t*)(H + idx) = pack2bf(v0, v1);
}
__device__ __forceinline__ void store_split(__nv_bfloat16* H, __nv_bfloat16* L,
                                            size_t idx, float v0, float v1) {
    __nv_bfloat16 h0 = __float2bfloat16(v0), h1 = __float2bfloat16(v1);
    __nv_bfloat16 l0 = __float2bfloat16(v0 - __bfloat162float(h0));
    __nv_bfloat16 l1 = __float2bfloat16(v1 - __bfloat162float(h1));
    *(__nv_bfloat162*)(H + idx) = __halves2bfloat162(h0, h1);
    *(__nv_bfloat162*)(L + idx) = __halves2bfloat162(l0, l1);
}
// 2^x via the MUFU pipe.
__device__ __forceinline__ float exp2p(float x) {
    x = fmaxf(x, -120.f);
    float r;
    asm("ex2.approx.f32 %0, %1;" : "=f"(r) : "f"(x));
    return r;
}

// ---------------- weight transpose + split -----------------------------------
__global__ void tsplit_kernel(const float* __restrict__ W, __nv_bfloat16* __restrict__ Wh,
                              __nv_bfloat16* __restrict__ Wl, int K, int N,
                              long sstr, long dstr) {
    W  += (size_t)blockIdx.z * sstr;
    Wh += (size_t)blockIdx.z * dstr;
    Wl += (size_t)blockIdx.z * dstr;
    __shared__ float tile[32][33];
    int n0 = blockIdx.x * 32, k0 = blockIdx.y * 32;
    int tx = threadIdx.x, ty = threadIdx.y;
#pragma unroll
    for (int i = 0; i < 4; i++)
        tile[ty + i * 8][tx] = W[(size_t)(k0 + ty + i * 8) * N + n0 + tx];
    __syncthreads();
#pragma unroll
    for (int i = 0; i < 4; i++) {
        int n = ty + i * 8;
        float v = tile[tx][n];
        __nv_bfloat16 h = __float2bfloat16(v);
        __nv_bfloat16 l = __float2bfloat16(v - __bfloat162float(h));
        size_t o = (size_t)(n0 + n) * K + k0 + tx;
        Wh[o] = h;
        Wl[o] = l;
    }
}

// Table-driven: nineteen 512x512 matrices in one launch (blockIdx.z).
struct TSTab { const float* src[19]; long dst[19]; };
__global__ void tsplit19_kernel(TSTab tab, __nv_bfloat16* __restrict__ WhB,
                                __nv_bfloat16* __restrict__ WlB) {
    const float* W = tab.src[blockIdx.z];
    __nv_bfloat16* Wh = WhB + tab.dst[blockIdx.z];
    __nv_bfloat16* Wl = WlB + tab.dst[blockIdx.z];
    __shared__ float tile[32][33];
    int n0 = blockIdx.x * 32, k0 = blockIdx.y * 32;
    int tx = threadIdx.x, ty = threadIdx.y;
#pragma unroll
    for (int i = 0; i < 4; i++)
        tile[ty + i * 8][tx] = W[(size_t)(k0 + ty + i * 8) * DM + n0 + tx];
    __syncthreads();
#pragma unroll
    for (int i = 0; i < 4; i++) {
        int n = ty + i * 8;
        float v = tile[tx][n];
        __nv_bfloat16 h = __float2bfloat16(v);
        __nv_bfloat16 l = __float2bfloat16(v - __bfloat162float(h));
        size_t o = (size_t)(n0 + n) * DM + k0 + tx;
        Wh[o] = h;
        Wl[o] = l;
    }
}

__global__ void bpack_kernel(const float* __restrict__ bq, const float* __restrict__ bk,
                             const float* __restrict__ bv, float* __restrict__ o) {
    int l = blockIdx.x, t = threadIdx.x;
    o[l * 3 * DM + t]          = bq[l * DM + t];
    o[l * 3 * DM + DM + t]     = bk[l * DM + t];
    o[l * 3 * DM + 2 * DM + t] = bv[l * DM + t];
}

// ------- pipelined HMMA GEMM: 64x64 warp tile (LDS-traffic-optimized) --------
// 128x128 block tile, 4 warps (2m x 2n), KC=32, 3-stage ring, 2 CTAs/SM.
#define KC 32
#define SPAD 40
#define SROW (SPAD * 2)                 // 80 B row stride
#define PRTC (128 * SROW)               // 10240 bytes per tile part
#define STGC (3 * PRTC)                 // stage stride: A | Bh | Bl
#define GEMM_SMEM (3 * STGC)            // 92160 bytes

template <int OP>
__global__ void __launch_bounds__(128, 2)
gemm_bf(const __nv_bfloat16* __restrict__ Ah,
        const __nv_bfloat16* __restrict__ Wh, const __nv_bfloat16* __restrict__ Wl,
        const float* __restrict__ bias, const float* __restrict__ res,
        float* __restrict__ Cf, __nv_bfloat16* __restrict__ Ch, __nv_bfloat16* __restrict__ Cl,
        int K, int N, int loN0, int loN1) {
    extern __shared__ char smem[];
    uint32_t sb = smem_u32(smem);

    int tid = threadIdx.x;
    int wid = tid >> 5, lid = tid & 31;
    int wm = wid & 1, wn = wid >> 1;       // 2m x 2n warps, warp tile 64x64
    int m0 = blockIdx.y * 128, n0 = blockIdx.x * 128;

    uint32_t aoff = (uint32_t)((wm * 64 + (lid & 15)) * SROW + (lid >> 4) * 16);
    int br = (lid & 7) + ((lid >> 4) << 3);
    uint32_t boff = (uint32_t)((wn * 64 + br) * SROW + ((lid >> 3) & 1) * 16);

    float acc[4][8][4];
#pragma unroll
    for (int i = 0; i < 4; i++)
#pragma unroll
        for (int j = 0; j < 8; j++)
#pragma unroll
            for (int u = 0; u < 4; u++) acc[i][j][u] = 0.f;

    const int nch = K / KC;
    // one stage = 512 chunks of 16B per part; 128 threads -> 4 chunks each per part
    auto load_stage = [&](int st, int k0) {
#pragma unroll
        for (int i = 0; i < 4; i++) {
            int id = tid + i * 128;
            int r = id >> 2, c = id & 3;
            uint32_t d = sb + (uint32_t)(st * STGC) + (uint32_t)(r * SROW + c * 16);
            cp16(d,            Ah + (size_t)(m0 + r) * K + k0 + c * 8);
            cp16(d + PRTC,     Wh + (size_t)(n0 + r) * K + k0 + c * 8);
            cp16(d + 2 * PRTC, Wl + (size_t)(n0 + r) * K + k0 + c * 8);
        }
        CP_COMMIT();
    };

    load_stage(0, 0);
    load_stage(1, KC);
    for (int ck = 0; ck < nch; ck++) {
        if (ck + 1 < nch) CP_WAIT1(); else CP_WAIT0();
        __syncthreads();
        int st = ck % 3;
        uint32_t AhB = sb + (uint32_t)(st * STGC);
        uint32_t BhB = AhB + PRTC, BlB = AhB + 2 * PRTC;
#pragma unroll
        for (int ks = 0; ks < KC; ks += 16) {
            uint32_t ah[4][4];
#pragma unroll
            for (int ma = 0; ma < 4; ma++)
                ldm_x4(ah[ma], AhB + aoff + (uint32_t)(ma * 16 * SROW + ks * 2));
            uint32_t bh[8][2], bl[8][2];
#pragma unroll
            for (int nq = 0; nq < 4; nq++) {
                uint32_t r4[4];
                uint32_t o = boff + (uint32_t)(nq * 16 * SROW + ks * 2);
                ldm_x4(r4, BhB + o);
                bh[nq * 2][0] = r4[0]; bh[nq * 2][1] = r4[1];
                bh[nq * 2 + 1][0] = r4[2]; bh[nq * 2 + 1][1] = r4[3];
                ldm_x4(r4, BlB + o);
                bl[nq * 2][0] = r4[0]; bl[nq * 2][1] = r4[1];
                bl[nq * 2 + 1][0] = r4[2]; bl[nq * 2 + 1][1] = r4[3];
            }
#pragma unroll
            for (int ma = 0; ma < 4; ma++)
#pragma unroll
                for (int na = 0; na < 8; na++) {
                    float* d = acc[ma][na];
                    mma_bf16(d, ah[ma], bh[na]);
                    mma_bf16(d, ah[ma], bl[na]);
                }
        }
        // prefetch chunk ck+2 into stage (ck+2)%3 == (ck-1)%3 — WAR-safe.
        if (ck + 2 < nch) load_stage((ck + 2) % 3, (ck + 2) * KC);
    }

    bool wantLo = Cl && (n0 >= loN0) && (n0 < loN1);
#pragma unroll
    for (int ma = 0; ma < 4; ma++) {
        int row0 = m0 + wm * 64 + ma * 16 + (lid >> 2);
#pragma unroll
        for (int na = 0; na < 8; na++) {
            int col = n0 + wn * 64 + na * 8 + (lid & 3) * 2;
            float b0 = bias ? bias[col] : 0.f;
            float b1 = bias ? bias[col + 1] : 0.f;
#pragma unroll
            for (int half = 0; half < 2; half++) {
                int row = row0 + half * 8;
                float v0 = acc[ma][na][half * 2 + 0] + b0;
                float v1 = acc[ma][na][half * 2 + 1] + b1;
                if (OP == 1) {
                    const float* rp = res + (size_t)row * N + col;
                    v0 += rp[0]; v1 += rp[1];
                }
                if (OP == 2) {
                    v0 = 0.5f * v0 * (1.0f + erff(v0 * 0.70710678118654752f));
                    v1 = 0.5f * v1 * (1.0f + erff(v1 * 0.70710678118654752f));
                }
                if (OP == 3) { v0 = tanhf(v0); v1 = tanhf(v1); }
                size_t idx = (size_t)row * N + col;
                if (Cf) *(float2*)(Cf + idx) = make_float2(v0, v1);
                if (Ch) {
                    if (wantLo) store_split(Ch, Cl, idx, v0, v1);
                    else        store_hi2(Ch, idx, v0, v1);
                }
            }
        }
    }
}

// ---------------- flash attention (2-pass QK, 1-pass PV, 2-stage cp.async) ---
#define FSP 72
#define FROW (FSP * 2)
#define FPRT (64 * FROW)
#define FSTG (3 * FPRT)
#define FLASH_SMEM (2 * FSTG)

__global__ void __launch_bounds__(128)
flash_kernel(const __nv_bfloat16* __restrict__ Xh, const __nv_bfloat16* __restrict__ Xl,
             __nv_bfloat16* __restrict__ Oh) {
    extern __shared__ char smem[];
    uint32_t sb = smem_u32(smem);
    int tid = threadIdx.x, w = tid >> 5, lid = tid & 31;
    int bh = blockIdx.x, b = bh >> 3, h = bh & 7;
    int q0 = blockIdx.y * 64;
    const int QS = 3 * DM;

#pragma unroll
    for (int u = 0; u < 4; u++) {
        int i = tid + u * 128;
        int r = i >> 3, c = i & 7;
        size_t g = (size_t)(b * TSEQ + q0 + r) * QS + h * HDIM + c * 8;
        *(uint4*)(smem + r * FROW + c * 16) = *(const uint4*)(Xh + g);
    }
    __syncthreads();
    uint32_t qfh[4][4];
    {
        uint32_t qoff = (uint32_t)((w * 16 + (lid & 15)) * FROW + (lid >> 4) * 16);
#pragma unroll
        for (int ks = 0; ks < 4; ks++)
            ldm_x4(qfh[ks], sb + qoff + ks * 32);
    }
    __syncthreads();

    float o[8][4];
#pragma unroll
    for (int n = 0; n < 8; n++)
#pragma unroll
        for (int j = 0; j < 4; j++) o[n][j] = 0.f;
    float m0 = -1e30f, m1 = -1e30f, l0 = 0.f, l1 = 0.f;
    const float SCL = 0.18033688011112042f;

    uint32_t koff = (uint32_t)(((lid & 7) + ((lid >> 4) << 3)) * FROW + ((lid >> 3) & 1) * 16);
    uint32_t voff = (uint32_t)((lid & 15) * FROW + (lid >> 4) * 16);

    auto load_chunk = [&](int st, int kt0) {
#pragma unroll
        for (int u = 0; u < 4; u++) {
            int i = tid + u * 128;
            int r = i >> 3, c = i & 7;
            size_t gk = (size_t)(b * TSEQ + kt0 + r) * QS + DM + h * HDIM + c * 8;
            uint32_t d = sb + (uint32_t)(st * FSTG) + (uint32_t)(r * FROW + c * 16);
            cp16(d,            Xh + gk);
            cp16(d + FPRT,     Xl + gk);
            cp16(d + 2 * FPRT, Xh + gk + DM);
        }
        CP_COMMIT();
    };

    load_chunk(0, 0);
    const int NCH = TSEQ / 64;
    for (int c = 0; c < NCH; c++) {
        CP_WAIT0();
        __syncthreads();
        if (c + 1 < NCH) load_chunk((c + 1) & 1, (c + 1) * 64);
        int st = c & 1;
        uint32_t sK0 = sb + (uint32_t)(st * FSTG);
        uint32_t sK1 = sK0 + FPRT;
        uint32_t sV0 = sK0 + 2 * FPRT;

        float s[8][4];
#pragma unroll
        for (int n = 0; n < 8; n++)
#pragma unroll
            for (int j = 0; j < 4; j++) s[n][j] = 0.f;
#pragma unroll
        for (int ks = 0; ks < 4; ks++) {
            uint32_t bkh[8][2], bkl[8][2];
#pragma unroll
            for (int nq = 0; nq < 4; nq++) {
                uint32_t r4[4];
                uint32_t ad = koff + (uint32_t)(nq * 16 * FROW + ks * 32);
                ldm_x4(r4, sK0 + ad);
                bkh[nq * 2][0] = r4[0]; bkh[nq * 2][1] = r4[1];
                bkh[nq * 2 + 1][0] = r4[2]; bkh[nq * 2 + 1][1] = r4[3];
                ldm_x4(r4, sK1 + ad);
                bkl[nq * 2][0] = r4[0]; bkl[nq * 2][1] = r4[1];
                bkl[nq * 2 + 1][0] = r4[2]; bkl[nq * 2 + 1][1] = r4[3];
            }
#pragma unroll
            for (int n = 0; n < 8; n++) {
                mma_bf16(s[n], qfh[ks], bkh[n]);
                mma_bf16(s[n], qfh[ks], bkl[n]);
            }
        }

        float mx0 = -1e30f, mx1 = -1e30f;
#pragma unroll
        for (int n = 0; n < 8; n++) {
            s[n][0] *= SCL; s[n][1] *= SCL; s[n][2] *= SCL; s[n][3] *= SCL;
            mx0 = fmaxf(mx0, fmaxf(s[n][0], s[n][1]));
            mx1 = fmaxf(mx1, fmaxf(s[n][2], s[n][3]));
        }
        mx0 = fmaxf(mx0, __shfl_xor_sync(0xffffffffu, mx0, 1));
        mx0 = fmaxf(mx0, __shfl_xor_sync(0xffffffffu, mx0, 2));
        mx1 = fmaxf(mx1, __shfl_xor_sync(0xffffffffu, mx1, 1));
        mx1 = fmaxf(mx1, __shfl_xor_sync(0xffffffffu, mx1, 2));
        float mn0 = fmaxf(m0, mx0), mn1 = fmaxf(m1, mx1);
        float c0 = exp2p(m0 - mn0), c1 = exp2p(m1 - mn1);
        m0 = mn0; m1 = mn1;
        float ps0 = 0.f, ps1 = 0.f;
#pragma unroll
        for (int n = 0; n < 8; n++) {
            s[n][0] = exp2p(s[n][0] - mn0);
            s[n][1] = exp2p(s[n][1] - mn0);
            s[n][2] = exp2p(s[n][2] - mn1);
            s[n][3] = exp2p(s[n][3] - mn1);
            ps0 += s[n][0] + s[n][1];
            ps1 += s[n][2] + s[n][3];
            o[n][0] *= c0; o[n][1] *= c0; o[n][2] *= c1; o[n][3] *= c1;
        }
        ps0 += __shfl_xor_sync(0xffffffffu, ps0, 1);
        ps0 += __shfl_xor_sync(0xffffffffu, ps0, 2);
        ps1 += __shfl_xor_sync(0xffffffffu, ps1, 1);
        ps1 += __shfl_xor_sync(0xffffffffu, ps1, 2);
        l0 = l0 * c0 + ps0;
        l1 = l1 * c1 + ps1;

        uint32_t pa[4][4];
#pragma unroll
        for (int t = 0; t < 4; t++) {
            pa[t][0] = pack2bf(s[2 * t][0],     s[2 * t][1]);
            pa[t][1] = pack2bf(s[2 * t][2],     s[2 * t][3]);
            pa[t][2] = pack2bf(s[2 * t + 1][0], s[2 * t + 1][1]);
            pa[t][3] = pack2bf(s[2 * t + 1][2], s[2 * t + 1][3]);
        }

#pragma unroll
        for (int kts = 0; kts < 4; kts++) {
            uint32_t bvh[8][2];
#pragma unroll
            for (int nd = 0; nd < 4; nd++) {
                uint32_t r4[4];
                uint32_t ad = voff + (uint32_t)(kts * 16 * FROW + nd * 32);
                ldm_x4t(r4, sV0 + ad);
                bvh[nd * 2][0] = r4[0]; bvh[nd * 2][1] = r4[1];
                bvh[nd * 2 + 1][0] = r4[2]; bvh[nd * 2 + 1][1] = r4[3];
            }
#pragma unroll
            for (int d = 0; d < 8; d++)
                mma_bf16(o[d], pa[kts], bvh[d]);
        }
    }

    float i0 = 1.f / l0, i1 = 1.f / l1;
    int r0 = q0 + w * 16 + (lid >> 2);
#pragma unroll
    for (int n = 0; n < 8; n++) {
        int col = h * HDIM + n * 8 + (lid & 3) * 2;
        store_hi2(Oh, (size_t)(b * TSEQ + r0) * DM + col,     o[n][0] * i0, o[n][1] * i0);
        store_hi2(Oh, (size_t)(b * TSEQ + r0 + 8) * DM + col, o[n][2] * i1, o[n][3] * i1);
    }
}

// ---------------- fused embed + layer-0 LN1 ----------------------------------
__global__ void embed_ln_kernel(const int* __restrict__ tokens, const float* __restrict__ emb,
                                float* __restrict__ x, __nv_bfloat16* __restrict__ oh,
                                const float* __restrict__ gw, const float* __restrict__ bw) {
    int row = blockIdx.x;
    int t = row & (TSEQ - 1);
    int tok = tokens[row];
    int tid = threadIdx.x;
    int d0 = tid * 4;
    float4 e = *(const float4*)&emb[(size_t)tok * DM + d0];
    float vals[4] = {e.x, e.y, e.z, e.w};
    const float c = -9.210340371976184f / (float)DM;
#pragma unroll
    for (int i = 0; i < 4; i++) {
        int d = d0 + i;
        float freq = expf((float)(2 * (d >> 1)) * c);
        float ang = (float)t * freq;
        vals[i] += (d & 1) ? cosf(ang) : sinf(ang);
    }
    size_t idx = (size_t)row * DM + d0;
    float4 ov = {vals[0], vals[1], vals[2], vals[3]};
    *(float4*)&x[idx] = ov;

    float s = vals[0] + vals[1] + vals[2] + vals[3];
    float ss = vals[0]*vals[0] + vals[1]*vals[1] + vals[2]*vals[2] + vals[3]*vals[3];
#pragma unroll
    for (int off = 16; off > 0; off >>= 1) {
        s  += __shfl_xor_sync(0xffffffffu, s,  off);
        ss += __shfl_xor_sync(0xffffffffu, ss, off);
    }
    __shared__ float sm[4], sm2[4];
    int w = tid >> 5;
    if ((tid & 31) == 0) { sm[w] = s; sm2[w] = ss; }
    __syncthreads();
    float S  = sm[0] + sm[1] + sm[2] + sm[3];
    float SS = sm2[0] + sm2[1] + sm2[2] + sm2[3];
    float mean = S * (1.0f / DM);
    float var  = SS * (1.0f / DM) - mean * mean;
    float rstd = rsqrtf(var + 1e-5f);
    float4 gv = *(const float4*)&gw[d0];
    float4 bv = *(const float4*)&bw[d0];
    float o0 = (vals[0] - mean) * rstd * gv.x + bv.x;
    float o1 = (vals[1] - mean) * rstd * gv.y + bv.y;
    float o2 = (vals[2] - mean) * rstd * gv.z + bv.z;
    float o3 = (vals[3] - mean) * rstd * gv.w + bv.w;
    store_hi2(oh, idx, o0, o1);
    store_hi2(oh, idx + 2, o2, o3);
}

// ---------------- layernorm: 2 rows per 256-thread block ---------------------
__global__ void __launch_bounds__(256)
ln_kernel(const float* __restrict__ in, float* __restrict__ outf,
          __nv_bfloat16* __restrict__ oh,
          const float* __restrict__ gw, const float* __restrict__ bw) {
    int tid = threadIdx.x;
    int half = tid >> 7;
    int htid = tid & 127;
    int row = blockIdx.x * 2 + half;
    float4 v = *(const float4*)&in[(size_t)row * DM + htid * 4];
    float s = v.x + v.y + v.z + v.w;
    float ss = v.x*v.x + v.y*v.y + v.z*v.z + v.w*v.w;
#pragma unroll
    for (int off = 16; off > 0; off >>= 1) {
        s  += __shfl_xor_sync(0xffffffffu, s,  off);
        ss += __shfl_xor_sync(0xffffffffu, ss, off);
    }
    __shared__ float sm[8], sm2[8];
    int w = tid >> 5;
    if ((tid & 31) == 0) { sm[w] = s; sm2[w] = ss; }
    __syncthreads();
    int base = half * 4;
    float S  = sm[base] + sm[base + 1] + sm[base + 2] + sm[base + 3];
    float SS = sm2[base] + sm2[base + 1] + sm2[base + 2] + sm2[base + 3];
    float mean = S * (1.0f / DM);
    float var  = SS * (1.0f / DM) - mean * mean;
    float rstd = rsqrtf(var + 1e-5f);
    float4 gv = *(const float4*)&gw[htid * 4];
    float4 bv = *(const float4*)&bw[htid * 4];
    float o0 = (v.x - mean) * rstd * gv.x + bv.x;
    float o1 = (v.y - mean) * rstd * gv.y + bv.y;
    float o2 = (v.z - mean) * rstd * gv.z + bv.z;
    float o3 = (v.w - mean) * rstd * gv.w + bv.w;
    size_t idx = (size_t)row * DM + htid * 4;
    if (outf) { float4 ov = {o0, o1, o2, o3}; *(float4*)&outf[idx] = ov; }
    if (oh) { store_hi2(oh, idx, o0, o1); store_hi2(oh, idx + 2, o2, o3); }
}

// ---------------- mean pool: split-T partials + reduce -----------------------
__global__ void pool1_kernel(const float* __restrict__ X, float* __restrict__ Part) {
    int bs = blockIdx.x;
    int b = bs >> 3, sl = bs & 7;
    int d = blockIdx.y * 128 + threadIdx.x;
    float s = 0.f;
    int t0 = sl * 128;
    for (int t = t0; t < t0 + 128; t++)
        s += X[((size_t)(b * TSEQ + t)) * DM + d];
    Part[(size_t)(sl * BSZ + b) * DM + d] = s;
}
__global__ void pool2_kernel(const float* __restrict__ Part, float* __restrict__ P) {
    int b = blockIdx.x;
    int d = blockIdx.y * 128 + threadIdx.x;
    float s = 0.f;
#pragma unroll
    for (int sl = 0; sl < 8; sl++)
        s += Part[(size_t)(sl * BSZ + b) * DM + d];
    P[b * DM + d] = s * (1.0f / TSEQ);
}

__global__ void cls_kernel(const float* __restrict__ P, const float* __restrict__ W,
                           const float* __restrict__ bias, float* __restrict__ out) {
    int b = blockIdx.x / NCLS;
    int c = blockIdx.x % NCLS;
    int tid = threadIdx.x;
    float s = 0.f;
    for (int d = tid; d < DM; d += 128)
        s += P[b * DM + d] * W[(size_t)d * NCLS + c];
#pragma unroll
    for (int off = 16; off > 0; off >>= 1) s += __shfl_xor_sync(0xffffffffu, s, off);
    __shared__ float sm[4];
    if ((tid & 31) == 0) sm[tid >> 5] = s;
    __syncthreads();
    if (tid == 0) out[b * NCLS + c] = sm[0] + sm[1] + sm[2] + sm[3] + bias[c];
}

// ---------------- launch ------------------------------------------------------
extern "C" void kernel_launch(void* const* d_in, const int* in_sizes, int n_in,
                              void* d_out, int out_size) {
    const int*   tokens = (const int*)  d_in[0];
    const float* emb    = (const float*)d_in[1];
    const float* Wq = (const float*)d_in[2];
    const float* bq = (const float*)d_in[3];
    const float* Wk = (const float*)d_in[4];
    const float* bk = (const float*)d_in[5];
    const float* Wv = (const float*)d_in[6];
    const float* bv = (const float*)d_in[7];
    const float* Wo = (const float*)d_in[8];
    const float* bo = (const float*)d_in[9];
    const float* ln1_g = (const float*)d_in[10];
    const float* ln1_b = (const float*)d_in[11];
    const float* ln2_g = (const float*)d_in[12];
    const float* ln2_b = (const float*)d_in[13];
    const float* W1 = (const float*)d_in[14];
    const float* b1 = (const float*)d_in[15];
    const float* W2 = (const float*)d_in[16];
    const float* b2 = (const float*)d_in[17];
    const float* heavy_w  = (const float*)d_in[18];
    const float* heavy_b  = (const float*)d_in[19];
    const float* heavy_a1 = (const float*)d_in[20];
    const float* heavy_a2 = (const float*)d_in[21];
    const float* norm_g = (const float*)d_in[22];
    const float* norm_b = (const float*)d_in[23];
    const float* cls_W  = (const float*)d_in[24];
    const float* cls_b  = (const float*)d_in[25];
    float* out = (float*)d_out;

    float *x, *tmp, *pool, *bqkv;
    __nv_bfloat16 *hh, *xh, *qkvh, *qkvl, *ath, *ffh, *wth, *wtl;
    cudaGetSymbolAddress((void**)&x,    g_x);
    cudaGetSymbolAddress((void**)&tmp,  g_t);
    cudaGetSymbolAddress((void**)&pool, g_pool);
    cudaGetSymbolAddress((void**)&bqkv, g_bqkv);
    cudaGetSymbolAddress((void**)&hh,   g_hh);
    cudaGetSymbolAddress((void**)&xh,   g_xh);
    cudaGetSymbolAddress((void**)&qkvh, g_qkvh);
    cudaGetSymbolAddress((void**)&qkvl, g_qkvl);
    cudaGetSymbolAddress((void**)&ath,  g_ath);
    cudaGetSymbolAddress((void**)&ffh,  g_ffh);
    cudaGetSymbolAddress((void**)&wth,  g_wt_hi);
    cudaGetSymbolAddress((void**)&wtl,  g_wt_lo);
    float* part = (float*)ffh;

    cudaFuncSetAttribute(gemm_bf<0>, cudaFuncAttributeMaxDynamicSharedMemorySize, GEMM_SMEM);
    cudaFuncSetAttribute(gemm_bf<1>, cudaFuncAttributeMaxDynamicSharedMemorySize, GEMM_SMEM);
    cudaFuncSetAttribute(gemm_bf<2>, cudaFuncAttributeMaxDynamicSharedMemorySize, GEMM_SMEM);
    cudaFuncSetAttribute(gemm_bf<3>, cudaFuncAttributeMaxDynamicSharedMemorySize, GEMM_SMEM);
    cudaFuncSetAttribute(flash_kernel, cudaFuncAttributeMaxDynamicSharedMemorySize, FLASH_SMEM);

    size_t hb = (size_t)LNUM * LSTRIDE;
    TSTab tab;
    for (int l = 0; l < LNUM; l++) {
        tab.src[l * 4 + 0] = Wq + (size_t)l * DM * DM;
        tab.src[l * 4 + 1] = Wk + (size_t)l * DM * DM;
        tab.src[l * 4 + 2] = Wv + (size_t)l * DM * DM;
        tab.src[l * 4 + 3] = Wo + (size_t)l * DM * DM;
        tab.dst[l * 4 + 0] = (long)l * LSTRIDE;
        tab.dst[l * 4 + 1] = (long)l * LSTRIDE + DM * DM;
        tab.dst[l * 4 + 2] = (long)l * LSTRIDE + 2 * DM * DM;
        tab.dst[l * 4 + 3] = (long)l * LSTRIDE + OFF_WO;
    }
    tab.src[16] = heavy_w;  tab.dst[16] = (long)hb;
    tab.src[17] = heavy_a1; tab.dst[17] = (long)hb + DM * DM;
    tab.src[18] = heavy_a2; tab.dst[18] = (long)hb + 2 * DM * DM;

    dim3 tb(32, 8);
    tsplit19_kernel<<<dim3(16, 16, 19), tb>>>(tab, wth, wtl);
    tsplit_kernel<<<dim3(FFD / 32, 16, LNUM), tb>>>(W1, wth + OFF_W1, wtl + OFF_W1, DM, FFD,
                                                    (long)DM * FFD, LSTRIDE);
    tsplit_kernel<<<dim3(16, FFD / 32, LNUM), tb>>>(W2, wth + OFF_W2, wtl + OFF_W2, FFD, DM,
                                                    (long)FFD * DM, LSTRIDE);
    bpack_kernel<<<LNUM, DM>>>(bq, bk, bv, bqkv);

    embed_ln_kernel<<<NTOK, 128>>>(tokens, emb, x, hh, ln1_g, ln1_b);

    dim3 gQKV(3 * DM / 128, NTOK / 128);
    dim3 gD(DM / 128, NTOK / 128);
    dim3 gF(FFD / 128, NTOK / 128);
    dim3 gFA(BSZ * HN, TSEQ / 64);
    const int NOLO = 1 << 30;
    const int LNG = NTOK / 2;

    for (int l = 0; l < LNUM; l++) {
        const __nv_bfloat16* wb_h = wth + (size_t)l * LSTRIDE;
        const __nv_bfloat16* wb_l = wtl + (size_t)l * LSTRIDE;

        if (l > 0)
            ln_kernel<<<LNG, 256>>>(x, nullptr, hh, ln1_g + l * DM, ln1_b + l * DM);
        gemm_bf<0><<<gQKV, 128, GEMM_SMEM>>>(hh, wb_h, wb_l, bqkv + l * 3 * DM,
                                             nullptr, nullptr, qkvh, qkvl, DM, 3 * DM,
                                             DM, 2 * DM);
        flash_kernel<<<gFA, 128, FLASH_SMEM>>>(qkvh, qkvl, ath);
        gemm_bf<1><<<gD, 128, GEMM_SMEM>>>(ath, wb_h + OFF_WO, wb_l + OFF_WO,
                                           bo + l * DM, x, x, nullptr, nullptr, DM, DM,
                                           0, NOLO);

        ln_kernel<<<LNG, 256>>>(x, nullptr, hh, ln2_g + l * DM, ln2_b + l * DM);
        gemm_bf<2><<<gF, 128, GEMM_SMEM>>>(hh, wb_h + OFF_W1, wb_l + OFF_W1,
                                           b1 + l * FFD, nullptr, nullptr, ffh, nullptr,
                                           DM, FFD, 0, NOLO);
        bool last = (l == LNUM - 1);
        gemm_bf<1><<<gD, 128, GEMM_SMEM>>>(ffh, wb_h + OFF_W2, wb_l + OFF_W2,
                                           b2 + l * DM, x, last ? nullptr : x,
                                           last ? xh : nullptr, nullptr, FFD, DM,
                                           0, NOLO);
    }

    gemm_bf<0><<<gD, 128, GEMM_SMEM>>>(xh, wth + hb, wtl + hb,
                                       nullptr, nullptr, nullptr, hh, nullptr, DM, DM, 0, NOLO);
    gemm_bf<0><<<gD, 128, GEMM_SMEM>>>(hh, wth + hb + DM * DM, wtl + hb + DM * DM,
                                       nullptr, nullptr, nullptr, qkvh, nullptr, DM, DM, 0, NOLO);
    gemm_bf<3><<<gD, 128, GEMM_SMEM>>>(qkvh, wth + hb + 2 * DM * DM, wtl + hb + 2 * DM * DM,
                                       heavy_b, nullptr, tmp, nullptr, nullptr, DM, DM, 0, NOLO);

    ln_kernel<<<LNG, 256>>>(tmp, x, nullptr, norm_g, norm_b);
    pool1_kernel<<<dim3(BSZ * 8, DM / 128), 128>>>(x, part);
    pool2_kernel<<<dim3(BSZ, DM / 128), 128>>>(part, pool);
    cls_kernel<<<BSZ * NCLS, 128>>>(pool, cls_W, cls_b, out);
    (void)in_sizes; (void)n_in; (void)out_size;
}

// round 17
// speedup vs baseline: 1.6524x; 1.6524x over previous
#include <cuda_runtime.h>
#include <cuda_bf16.h>
#include <math.h>
#include <stdint.h>

#define BSZ 8
#define TSEQ 1024
#define DM 512
#define HN 8
#define HDIM 64
#define LNUM 4
#define FFD 2048
#define NCLS 10
#define NTOK (BSZ * TSEQ)

// ---------------- scratch ----------------------------------------------------
__device__ float g_x [NTOK * DM];
__device__ float g_t [NTOK * DM];
__device__ float g_pool[BSZ * DM];
__device__ float g_bqkv[LNUM * 3 * DM];
__device__ __nv_bfloat16 g_hh [NTOK * DM];
__device__ __nv_bfloat16 g_xh [NTOK * DM];
__device__ __nv_bfloat16 g_qkvh[NTOK * 3 * DM], g_qkvl[NTOK * 3 * DM];
__device__ __nv_bfloat16 g_ath[NTOK * DM];
__device__ __nv_bfloat16 g_ffh[NTOK * FFD];

#define LSTRIDE (3 * DM * DM + DM * DM + DM * FFD + FFD * DM)
#define WT_TOT  (LNUM * LSTRIDE + 3 * DM * DM)
__device__ __nv_bfloat16 g_wt_hi[WT_TOT];
__device__ __nv_bfloat16 g_wt_lo[WT_TOT];
#define OFF_WO (3 * DM * DM)
#define OFF_W1 (OFF_WO + DM * DM)
#define OFF_W2 (OFF_W1 + DM * FFD)

// ---------------- helpers ----------------------------------------------------
__device__ __forceinline__ uint32_t smem_u32(const void* p) {
    uint32_t a;
    asm("{ .reg .u64 t; cvta.to.shared.u64 t, %1; cvt.u32.u64 %0, t; }" : "=r"(a) : "l"(p));
    return a;
}
__device__ __forceinline__ void ldm_x4(uint32_t* r, uint32_t addr) {
    asm volatile("ldmatrix.sync.aligned.m8n8.x4.shared.b16 {%0,%1,%2,%3}, [%4];"
                 : "=r"(r[0]), "=r"(r[1]), "=r"(r[2]), "=r"(r[3]) : "r"(addr));
}
__device__ __forceinline__ void ldm_x4t(uint32_t* r, uint32_t addr) {
    asm volatile("ldmatrix.sync.aligned.m8n8.x4.trans.shared.b16 {%0,%1,%2,%3}, [%4];"
                 : "=r"(r[0]), "=r"(r[1]), "=r"(r[2]), "=r"(r[3]) : "r"(addr));
}
__device__ __forceinline__ void mma_bf16(float* d, const uint32_t* a, const uint32_t* b) {
    asm volatile("mma.sync.aligned.m16n8k16.row.col.f32.bf16.bf16.f32 "
                 "{%0,%1,%2,%3}, {%4,%5,%6,%7}, {%8,%9}, {%0,%1,%2,%3};"
                 : "+f"(d[0]), "+f"(d[1]), "+f"(d[2]), "+f"(d[3])
                 : "r"(a[0]), "r"(a[1]), "r"(a[2]), "r"(a[3]), "r"(b[0]), "r"(b[1]));
}
__device__ __forceinline__ void cp16(uint32_t dst, const void* src) {
    asm volatile("cp.async.cg.shared.global [%0], [%1], 16;" :: "r"(dst), "l"(src));
}
#define CP_COMMIT() asm volatile("cp.async.commit_group;" ::: "memory")
#define CP_WAIT1()  asm volatile("cp.async.wait_group 1;" ::: "memory")
#define CP_WAIT0()  asm volatile("cp.async.wait_group 0;" ::: "memory")

__device__ __forceinline__ uint32_t pack2bf(float lo, float hi) {
    uint32_t r;
    asm("cvt.rn.bf16x2.f32 %0, %1, %2;" : "=r"(r) : "f"(hi), "f"(lo));
    return r;
}
__device__ __forceinline__ void store_hi2(__nv_bfloat16* H, size_t idx, float v0, float v1) {
    *(uint32_t*)(H + idx) = pack2bf(v0, v1);
}
__device__ __forceinline__ void store_split(__nv_bfloat16* H, __nv_bfloat16* L,
                                            size_t idx, float v0, float v1) {
    __nv_bfloat16 h0 = __float2bfloat16(v0), h1 = __float2bfloat16(v1);
    __nv_bfloat16 l0 = __float2bfloat16(v0 - __bfloat162float(h0));
    __nv_bfloat16 l1 = __float2bfloat16(v1 - __bfloat162float(h1));
    *(__nv_bfloat162*)(H + idx) = __halves2bfloat162(h0, h1);
    *(__nv_bfloat162*)(L + idx) = __halves2bfloat162(l0, l1);
}
// 2^x via the MUFU pipe (offloads softmax from the FMA pipe).
__device__ __forceinline__ float exp2p(float x) {
    x = fmaxf(x, -120.f);
    float r;
    asm("ex2.approx.f32 %0, %1;" : "=f"(r) : "f"(x));
    return r;
}

// ---------------- weight transpose + split -----------------------------------
__global__ void tsplit_kernel(const float* __restrict__ W, __nv_bfloat16* __restrict__ Wh,
                              __nv_bfloat16* __restrict__ Wl, int K, int N,
                              long sstr, long dstr) {
    W  += (size_t)blockIdx.z * sstr;
    Wh += (size_t)blockIdx.z * dstr;
    Wl += (size_t)blockIdx.z * dstr;
    __shared__ float tile[32][33];
    int n0 = blockIdx.x * 32, k0 = blockIdx.y * 32;
    int tx = threadIdx.x, ty = threadIdx.y;
#pragma unroll
    for (int i = 0; i < 4; i++)
        tile[ty + i * 8][tx] = W[(size_t)(k0 + ty + i * 8) * N + n0 + tx];
    __syncthreads();
#pragma unroll
    for (int i = 0; i < 4; i++) {
        int n = ty + i * 8;
        float v = tile[tx][n];
        __nv_bfloat16 h = __float2bfloat16(v);
        __nv_bfloat16 l = __float2bfloat16(v - __bfloat162float(h));
        size_t o = (size_t)(n0 + n) * K + k0 + tx;
        Wh[o] = h;
        Wl[o] = l;
    }
}

// Table-driven version: nineteen 512x512 matrices in one launch (blockIdx.z).
struct TSTab { const float* src[19]; long dst[19]; };
__global__ void tsplit19_kernel(TSTab tab, __nv_bfloat16* __restrict__ WhB,
                                __nv_bfloat16* __restrict__ WlB) {
    const float* W = tab.src[blockIdx.z];
    __nv_bfloat16* Wh = WhB + tab.dst[blockIdx.z];
    __nv_bfloat16* Wl = WlB + tab.dst[blockIdx.z];
    __shared__ float tile[32][33];
    int n0 = blockIdx.x * 32, k0 = blockIdx.y * 32;
    int tx = threadIdx.x, ty = threadIdx.y;
#pragma unroll
    for (int i = 0; i < 4; i++)
        tile[ty + i * 8][tx] = W[(size_t)(k0 + ty + i * 8) * DM + n0 + tx];
    __syncthreads();
#pragma unroll
    for (int i = 0; i < 4; i++) {
        int n = ty + i * 8;
        float v = tile[tx][n];
        __nv_bfloat16 h = __float2bfloat16(v);
        __nv_bfloat16 l = __float2bfloat16(v - __bfloat162float(h));
        size_t o = (size_t)(n0 + n) * DM + k0 + tx;
        Wh[o] = h;
        Wl[o] = l;
    }
}

__global__ void bpack_kernel(const float* __restrict__ bq, const float* __restrict__ bk,
                             const float* __restrict__ bv, float* __restrict__ o) {
    int l = blockIdx.x, t = threadIdx.x;
    o[l * 3 * DM + t]          = bq[l * DM + t];
    o[l * 3 * DM + DM + t]     = bk[l * DM + t];
    o[l * 3 * DM + 2 * DM + t] = bv[l * DM + t];
}

// ---------------- pipelined HMMA GEMM (2-pass AhBh + AhBl, 3-stage ring) -----
#define KC 32
#define SPAD 40
#define PRTC (128 * SPAD * 2)           // 10240 bytes per tile part
#define STGC (3 * PRTC)                 // stage stride: A | Bh | Bl
#define GEMM_SMEM (3 * STGC)            // 92160 bytes

// loN0/loN1: global-N range for which Cl (lo split output) is written.
template <int OP>
__global__ void __launch_bounds__(256, 2)
gemm_bf(const __nv_bfloat16* __restrict__ Ah,
        const __nv_bfloat16* __restrict__ Wh, const __nv_bfloat16* __restrict__ Wl,
        const float* __restrict__ bias, const float* __restrict__ res,
        float* __restrict__ Cf, __nv_bfloat16* __restrict__ Ch, __nv_bfloat16* __restrict__ Cl,
        int K, int N, int loN0, int loN1) {
    extern __shared__ char smem[];
    uint32_t sb = smem_u32(smem);

    int tid = threadIdx.x;
    int wid = tid >> 5, lid = tid & 31;
    int wm = wid & 3, wn = wid >> 2;
    int m0 = blockIdx.y * 128, n0 = blockIdx.x * 128;

    int ar = lid & 15, acb = lid >> 4;
    uint32_t aoff = (uint32_t)((wm * 32 + ar) * (SPAD * 2) + acb * 16);
    int br = (lid & 7) + ((lid >> 4) << 3);
    int bcb = (lid >> 3) & 1;
    uint32_t boff = (uint32_t)((wn * 64 + br) * (SPAD * 2) + bcb * 16);

    float acc[2][8][4];
#pragma unroll
    for (int i = 0; i < 2; i++)
#pragma unroll
        for (int j = 0; j < 8; j++)
#pragma unroll
            for (int u = 0; u < 4; u++) acc[i][j][u] = 0.f;

    const int nch = K / KC;
    // one stage = 512 chunks of 16B per part; 256 threads -> 2 chunks each per part
    auto load_stage = [&](int st, int k0) {
#pragma unroll
        for (int i = 0; i < 2; i++) {
            int id = tid + i * 256;
            int r = id >> 2, c = id & 3;
            uint32_t d = sb + (uint32_t)(st * STGC) + (uint32_t)(r * (SPAD * 2) + c * 16);
            cp16(d,            Ah + (size_t)(m0 + r) * K + k0 + c * 8);
            cp16(d + PRTC,     Wh + (size_t)(n0 + r) * K + k0 + c * 8);
            cp16(d + 2 * PRTC, Wl + (size_t)(n0 + r) * K + k0 + c * 8);
        }
        CP_COMMIT();
    };

    load_stage(0, 0);
    load_stage(1, KC);
    for (int ck = 0; ck < nch; ck++) {
        if (ck + 1 < nch) CP_WAIT1(); else CP_WAIT0();
        __syncthreads();
        int st = ck % 3;
        uint32_t AhB = sb + (uint32_t)(st * STGC);
        uint32_t BhB = AhB + PRTC, BlB = AhB + 2 * PRTC;
#pragma unroll
        for (int ks = 0; ks < KC; ks += 16) {
            uint32_t ah[2][4];
#pragma unroll
            for (int ma = 0; ma < 2; ma++)
                ldm_x4(ah[ma], AhB + aoff + (uint32_t)(ma * 16 * SPAD * 2 + ks * 2));
#pragma unroll
            for (int nh = 0; nh < 2; nh++) {
                uint32_t bh[4][2], bl[4][2];
#pragma unroll
                for (int nq = 0; nq < 2; nq++) {
                    uint32_t r4[4];
                    uint32_t o = boff + (uint32_t)((nh * 32 + nq * 16) * SPAD * 2 + ks * 2);
                    ldm_x4(r4, BhB + o);
                    bh[nq * 2][0] = r4[0]; bh[nq * 2][1] = r4[1];
                    bh[nq * 2 + 1][0] = r4[2]; bh[nq * 2 + 1][1] = r4[3];
                    ldm_x4(r4, BlB + o);
                    bl[nq * 2][0] = r4[0]; bl[nq * 2][1] = r4[1];
                    bl[nq * 2 + 1][0] = r4[2]; bl[nq * 2 + 1][1] = r4[3];
                }
#pragma unroll
                for (int ma = 0; ma < 2; ma++)
#pragma unroll
                    for (int na = 0; na < 4; na++) {
                        float* d = acc[ma][nh * 4 + na];
                        mma_bf16(d, ah[ma], bh[na]);
                        mma_bf16(d, ah[ma], bl[na]);
                    }
            }
        }
        // prefetch chunk ck+2 into stage (ck+2)%3 == (ck-1)%3 — WAR-safe.
        if (ck + 2 < nch) load_stage((ck + 2) % 3, (ck + 2) * KC);
    }

    bool wantLo = Cl && (n0 >= loN0) && (n0 < loN1);
#pragma unroll
    for (int ma = 0; ma < 2; ma++) {
        int row0 = m0 + wm * 32 + ma * 16 + (lid >> 2);
#pragma unroll
        for (int na = 0; na < 8; na++) {
            int col = n0 + wn * 64 + na * 8 + (lid & 3) * 2;
            float b0 = bias ? bias[col] : 0.f;
            float b1 = bias ? bias[col + 1] : 0.f;
#pragma unroll
            for (int half = 0; half < 2; half++) {
                int row = row0 + half * 8;
                float v0 = acc[ma][na][half * 2 + 0] + b0;
                float v1 = acc[ma][na][half * 2 + 1] + b1;
                if (OP == 1) {
                    const float* rp = res + (size_t)row * N + col;
                    v0 += rp[0]; v1 += rp[1];
                }
                if (OP == 2) {
                    v0 = 0.5f * v0 * (1.0f + erff(v0 * 0.70710678118654752f));
                    v1 = 0.5f * v1 * (1.0f + erff(v1 * 0.70710678118654752f));
                }
                if (OP == 3) { v0 = tanhf(v0); v1 = tanhf(v1); }
                size_t idx = (size_t)row * N + col;
                if (Cf) *(float2*)(Cf + idx) = make_float2(v0, v1);
                if (Ch) {
                    if (wantLo) store_split(Ch, Cl, idx, v0, v1);
                    else        store_hi2(Ch, idx, v0, v1);
                }
            }
        }
    }
}

// ---------------- flash attention (2-pass QK, 1-pass PV, 2-stage cp.async) ---
#define FSP 72
#define FROW (FSP * 2)                  // 144 B row stride
#define FPRT (64 * FROW)                // 9216 B per tensor tile
#define FSTG (3 * FPRT)                 // stage: Khi | Klo | V = 27648 B
#define FLASH_SMEM (2 * FSTG)           // 55296 B

__global__ void __launch_bounds__(128)
flash_kernel(const __nv_bfloat16* __restrict__ Xh, const __nv_bfloat16* __restrict__ Xl,
             __nv_bfloat16* __restrict__ Oh) {
    extern __shared__ char smem[];
    uint32_t sb = smem_u32(smem);
    int tid = threadIdx.x, w = tid >> 5, lid = tid & 31;
    int bh = blockIdx.x, b = bh >> 3, h = bh & 7;
    int q0 = blockIdx.y * 64;
    const int QS = 3 * DM;

    // ---- stage Q hi into stage0-Khi, extract A-frags ----
#pragma unroll
    for (int u = 0; u < 4; u++) {
        int i = tid + u * 128;
        int r = i >> 3, c = i & 7;
        size_t g = (size_t)(b * TSEQ + q0 + r) * QS + h * HDIM + c * 8;
        *(uint4*)(smem + r * FROW + c * 16) = *(const uint4*)(Xh + g);
    }
    __syncthreads();
    uint32_t qfh[4][4];
    {
        uint32_t qoff = (uint32_t)((w * 16 + (lid & 15)) * FROW + (lid >> 4) * 16);
#pragma unroll
        for (int ks = 0; ks < 4; ks++)
            ldm_x4(qfh[ks], sb + qoff + ks * 32);
    }
    __syncthreads();   // all warps done reading Q before stage0 is overwritten

    float o[8][4];
#pragma unroll
    for (int n = 0; n < 8; n++)
#pragma unroll
        for (int j = 0; j < 4; j++) o[n][j] = 0.f;
    float m0 = -1e30f, m1 = -1e30f, l0 = 0.f, l1 = 0.f;
    const float SCL = 0.18033688011112042f;   // 0.125 * log2(e)

    uint32_t koff = (uint32_t)(((lid & 7) + ((lid >> 4) << 3)) * FROW + ((lid >> 3) & 1) * 16);
    uint32_t voff = (uint32_t)((lid & 15) * FROW + (lid >> 4) * 16);

    auto load_chunk = [&](int st, int kt0) {
#pragma unroll
        for (int u = 0; u < 4; u++) {
            int i = tid + u * 128;
            int r = i >> 3, c = i & 7;
            size_t gk = (size_t)(b * TSEQ + kt0 + r) * QS + DM + h * HDIM + c * 8;
            uint32_t d = sb + (uint32_t)(st * FSTG) + (uint32_t)(r * FROW + c * 16);
            cp16(d,            Xh + gk);          // K hi
            cp16(d + FPRT,     Xl + gk);          // K lo
            cp16(d + 2 * FPRT, Xh + gk + DM);     // V hi
        }
        CP_COMMIT();
    };

    load_chunk(0, 0);
    const int NCH = TSEQ / 64;
    for (int c = 0; c < NCH; c++) {
        CP_WAIT0();
        __syncthreads();
        if (c + 1 < NCH) load_chunk((c + 1) & 1, (c + 1) * 64);  // overlaps compute(c)
        int st = c & 1;
        uint32_t sK0 = sb + (uint32_t)(st * FSTG);
        uint32_t sK1 = sK0 + FPRT;
        uint32_t sV0 = sK0 + 2 * FPRT;

        // S = Q K^T : Qh*Kh + Qh*Kl
        float s[8][4];
#pragma unroll
        for (int n = 0; n < 8; n++)
#pragma unroll
            for (int j = 0; j < 4; j++) s[n][j] = 0.f;
#pragma unroll
        for (int ks = 0; ks < 4; ks++) {
            uint32_t bkh[8][2], bkl[8][2];
#pragma unroll
            for (int nq = 0; nq < 4; nq++) {
                uint32_t r4[4];
                uint32_t ad = koff + (uint32_t)(nq * 16 * FROW + ks * 32);
                ldm_x4(r4, sK0 + ad);
                bkh[nq * 2][0] = r4[0]; bkh[nq * 2][1] = r4[1];
                bkh[nq * 2 + 1][0] = r4[2]; bkh[nq * 2 + 1][1] = r4[3];
                ldm_x4(r4, sK1 + ad);
                bkl[nq * 2][0] = r4[0]; bkl[nq * 2][1] = r4[1];
                bkl[nq * 2 + 1][0] = r4[2]; bkl[nq * 2 + 1][1] = r4[3];
            }
#pragma unroll
            for (int n = 0; n < 8; n++) {
                mma_bf16(s[n], qfh[ks], bkh[n]);
                mma_bf16(s[n], qfh[ks], bkl[n]);
            }
        }

        // online softmax (log2 domain, exp on MUFU pipe)
        float mx0 = -1e30f, mx1 = -1e30f;
#pragma unroll
        for (int n = 0; n < 8; n++) {
            s[n][0] *= SCL; s[n][1] *= SCL; s[n][2] *= SCL; s[n][3] *= SCL;
            mx0 = fmaxf(mx0, fmaxf(s[n][0], s[n][1]));
            mx1 = fmaxf(mx1, fmaxf(s[n][2], s[n][3]));
        }
        mx0 = fmaxf(mx0, __shfl_xor_sync(0xffffffffu, mx0, 1));
        mx0 = fmaxf(mx0, __shfl_xor_sync(0xffffffffu, mx0, 2));
        mx1 = fmaxf(mx1, __shfl_xor_sync(0xffffffffu, mx1, 1));
        mx1 = fmaxf(mx1, __shfl_xor_sync(0xffffffffu, mx1, 2));
        float mn0 = fmaxf(m0, mx0), mn1 = fmaxf(m1, mx1);
        float c0 = exp2p(m0 - mn0), c1 = exp2p(m1 - mn1);
        m0 = mn0; m1 = mn1;
        float ps0 = 0.f, ps1 = 0.f;
#pragma unroll
        for (int n = 0; n < 8; n++) {
            s[n][0] = exp2p(s[n][0] - mn0);
            s[n][1] = exp2p(s[n][1] - mn0);
            s[n][2] = exp2p(s[n][2] - mn1);
            s[n][3] = exp2p(s[n][3] - mn1);
            ps0 += s[n][0] + s[n][1];
            ps1 += s[n][2] + s[n][3];
            o[n][0] *= c0; o[n][1] *= c0; o[n][2] *= c1; o[n][3] *= c1;
        }
        ps0 += __shfl_xor_sync(0xffffffffu, ps0, 1);
        ps0 += __shfl_xor_sync(0xffffffffu, ps0, 2);
        ps1 += __shfl_xor_sync(0xffffffffu, ps1, 1);
        ps1 += __shfl_xor_sync(0xffffffffu, ps1, 2);
        l0 = l0 * c0 + ps0;
        l1 = l1 * c1 + ps1;

        // P -> bf16 A-frags
        uint32_t pa[4][4];
#pragma unroll
        for (int t = 0; t < 4; t++) {
            pa[t][0] = pack2bf(s[2 * t][0],     s[2 * t][1]);
            pa[t][1] = pack2bf(s[2 * t][2],     s[2 * t][3]);
            pa[t][2] = pack2bf(s[2 * t + 1][0], s[2 * t + 1][1]);
            pa[t][3] = pack2bf(s[2 * t + 1][2], s[2 * t + 1][3]);
        }

        // O += P Vh, V via ldmatrix.trans
#pragma unroll
        for (int kts = 0; kts < 4; kts++) {
            uint32_t bvh[8][2];
#pragma unroll
            for (int nd = 0; nd < 4; nd++) {
                uint32_t r4[4];
                uint32_t ad = voff + (uint32_t)(kts * 16 * FROW + nd * 32);
                ldm_x4t(r4, sV0 + ad);
                bvh[nd * 2][0] = r4[0]; bvh[nd * 2][1] = r4[1];
                bvh[nd * 2 + 1][0] = r4[2]; bvh[nd * 2 + 1][1] = r4[3];
            }
#pragma unroll
            for (int d = 0; d < 8; d++)
                mma_bf16(o[d], pa[kts], bvh[d]);
        }
    }

    float i0 = 1.f / l0, i1 = 1.f / l1;
    int r0 = q0 + w * 16 + (lid >> 2);
#pragma unroll
    for (int n = 0; n < 8; n++) {
        int col = h * HDIM + n * 8 + (lid & 3) * 2;
        store_hi2(Oh, (size_t)(b * TSEQ + r0) * DM + col,     o[n][0] * i0, o[n][1] * i0);
        store_hi2(Oh, (size_t)(b * TSEQ + r0 + 8) * DM + col, o[n][2] * i1, o[n][3] * i1);
    }
}

// ---------------- fused embed + layer-0 LN1 ----------------------------------
__global__ void embed_ln_kernel(const int* __restrict__ tokens, const float* __restrict__ emb,
                                float* __restrict__ x, __nv_bfloat16* __restrict__ oh,
                                const float* __restrict__ gw, const float* __restrict__ bw) {
    int row = blockIdx.x;
    int t = row & (TSEQ - 1);
    int tok = tokens[row];
    int tid = threadIdx.x;
    int d0 = tid * 4;
    float4 e = *(const float4*)&emb[(size_t)tok * DM + d0];
    float vals[4] = {e.x, e.y, e.z, e.w};
    const float c = -9.210340371976184f / (float)DM;
#pragma unroll
    for (int i = 0; i < 4; i++) {
        int d = d0 + i;
        float freq = expf((float)(2 * (d >> 1)) * c);
        float ang = (float)t * freq;
        vals[i] += (d & 1) ? cosf(ang) : sinf(ang);
    }
    size_t idx = (size_t)row * DM + d0;
    float4 ov = {vals[0], vals[1], vals[2], vals[3]};
    *(float4*)&x[idx] = ov;

    float s = vals[0] + vals[1] + vals[2] + vals[3];
    float ss = vals[0]*vals[0] + vals[1]*vals[1] + vals[2]*vals[2] + vals[3]*vals[3];
#pragma unroll
    for (int off = 16; off > 0; off >>= 1) {
        s  += __shfl_xor_sync(0xffffffffu, s,  off);
        ss += __shfl_xor_sync(0xffffffffu, ss, off);
    }
    __shared__ float sm[4], sm2[4];
    int w = tid >> 5;
    if ((tid & 31) == 0) { sm[w] = s; sm2[w] = ss; }
    __syncthreads();
    float S  = sm[0] + sm[1] + sm[2] + sm[3];
    float SS = sm2[0] + sm2[1] + sm2[2] + sm2[3];
    float mean = S * (1.0f / DM);
    float var  = SS * (1.0f / DM) - mean * mean;
    float rstd = rsqrtf(var + 1e-5f);
    float4 gv = *(const float4*)&gw[d0];
    float4 bv = *(const float4*)&bw[d0];
    float o0 = (vals[0] - mean) * rstd * gv.x + bv.x;
    float o1 = (vals[1] - mean) * rstd * gv.y + bv.y;
    float o2 = (vals[2] - mean) * rstd * gv.z + bv.z;
    float o3 = (vals[3] - mean) * rstd * gv.w + bv.w;
    store_hi2(oh, idx, o0, o1);
    store_hi2(oh, idx + 2, o2, o3);
}

// ---------------- layernorm: 2 rows per 256-thread block ---------------------
__global__ void __launch_bounds__(256)
ln_kernel(const float* __restrict__ in, float* __restrict__ outf,
          __nv_bfloat16* __restrict__ oh,
          const float* __restrict__ gw, const float* __restrict__ bw) {
    int tid = threadIdx.x;
    int half = tid >> 7;                // 0 or 1
    int htid = tid & 127;
    int row = blockIdx.x * 2 + half;
    float4 v = *(const float4*)&in[(size_t)row * DM + htid * 4];
    float s = v.x + v.y + v.z + v.w;
    float ss = v.x*v.x + v.y*v.y + v.z*v.z + v.w*v.w;
#pragma unroll
    for (int off = 16; off > 0; off >>= 1) {
        s  += __shfl_xor_sync(0xffffffffu, s,  off);
        ss += __shfl_xor_sync(0xffffffffu, ss, off);
    }
    __shared__ float sm[8], sm2[8];
    int w = tid >> 5;                   // 0..7 (0-3 row0, 4-7 row1)
    if ((tid & 31) == 0) { sm[w] = s; sm2[w] = ss; }
    __syncthreads();
    int base = half * 4;
    float S  = sm[base] + sm[base + 1] + sm[base + 2] + sm[base + 3];
    float SS = sm2[base] + sm2[base + 1] + sm2[base + 2] + sm2[base + 3];
    float mean = S * (1.0f / DM);
    float var  = SS * (1.0f / DM) - mean * mean;
    float rstd = rsqrtf(var + 1e-5f);
    float4 gv = *(const float4*)&gw[htid * 4];
    float4 bv = *(const float4*)&bw[htid * 4];
    float o0 = (v.x - mean) * rstd * gv.x + bv.x;
    float o1 = (v.y - mean) * rstd * gv.y + bv.y;
    float o2 = (v.z - mean) * rstd * gv.z + bv.z;
    float o3 = (v.w - mean) * rstd * gv.w + bv.w;
    size_t idx = (size_t)row * DM + htid * 4;
    if (outf) { float4 ov = {o0, o1, o2, o3}; *(float4*)&outf[idx] = ov; }
    if (oh) { store_hi2(oh, idx, o0, o1); store_hi2(oh, idx + 2, o2, o3); }
}

// ---------------- mean pool: split-T partials + reduce -----------------------
__global__ void pool1_kernel(const float* __restrict__ X, float* __restrict__ Part) {
    int bs = blockIdx.x;                // b*8 + slice
    int b = bs >> 3, sl = bs & 7;
    int d = blockIdx.y * 128 + threadIdx.x;
    float s = 0.f;
    int t0 = sl * 128;
    for (int t = t0; t < t0 + 128; t++)
        s += X[((size_t)(b * TSEQ + t)) * DM + d];
    Part[(size_t)(sl * BSZ + b) * DM + d] = s;
}
__global__ void pool2_kernel(const float* __restrict__ Part, float* __restrict__ P) {
    int b = blockIdx.x;
    int d = blockIdx.y * 128 + threadIdx.x;
    float s = 0.f;
#pragma unroll
    for (int sl = 0; sl < 8; sl++)
        s += Part[(size_t)(sl * BSZ + b) * DM + d];
    P[b * DM + d] = s * (1.0f / TSEQ);
}

__global__ void cls_kernel(const float* __restrict__ P, const float* __restrict__ W,
                           const float* __restrict__ bias, float* __restrict__ out) {
    int b = blockIdx.x / NCLS;
    int c = blockIdx.x % NCLS;
    int tid = threadIdx.x;
    float s = 0.f;
    for (int d = tid; d < DM; d += 128)
        s += P[b * DM + d] * W[(size_t)d * NCLS + c];
#pragma unroll
    for (int off = 16; off > 0; off >>= 1) s += __shfl_xor_sync(0xffffffffu, s, off);
    __shared__ float sm[4];
    if ((tid & 31) == 0) sm[tid >> 5] = s;
    __syncthreads();
    if (tid == 0) out[b * NCLS + c] = sm[0] + sm[1] + sm[2] + sm[3] + bias[c];
}

// ---------------- launch ------------------------------------------------------
extern "C" void kernel_launch(void* const* d_in, const int* in_sizes, int n_in,
                              void* d_out, int out_size) {
    const int*   tokens = (const int*)  d_in[0];
    const float* emb    = (const float*)d_in[1];
    const float* Wq = (const float*)d_in[2];
    const float* bq = (const float*)d_in[3];
    const float* Wk = (const float*)d_in[4];
    const float* bk = (const float*)d_in[5];
    const float* Wv = (const float*)d_in[6];
    const float* bv = (const float*)d_in[7];
    const float* Wo = (const float*)d_in[8];
    const float* bo = (const float*)d_in[9];
    const float* ln1_g = (const float*)d_in[10];
    const float* ln1_b = (const float*)d_in[11];
    const float* ln2_g = (const float*)d_in[12];
    const float* ln2_b = (const float*)d_in[13];
    const float* W1 = (const float*)d_in[14];
    const float* b1 = (const float*)d_in[15];
    const float* W2 = (const float*)d_in[16];
    const float* b2 = (const float*)d_in[17];
    const float* heavy_w  = (const float*)d_in[18];
    const float* heavy_b  = (const float*)d_in[19];
    const float* heavy_a1 = (const float*)d_in[20];
    const float* heavy_a2 = (const float*)d_in[21];
    const float* norm_g = (const float*)d_in[22];
    const float* norm_b = (const float*)d_in[23];
    const float* cls_W  = (const float*)d_in[24];
    const float* cls_b  = (const float*)d_in[25];
    float* out = (float*)d_out;

    float *x, *tmp, *pool, *bqkv;
    __nv_bfloat16 *hh, *xh, *qkvh, *qkvl, *ath, *ffh, *wth, *wtl;
    cudaGetSymbolAddress((void**)&x,    g_x);
    cudaGetSymbolAddress((void**)&tmp,  g_t);
    cudaGetSymbolAddress((void**)&pool, g_pool);
    cudaGetSymbolAddress((void**)&bqkv, g_bqkv);
    cudaGetSymbolAddress((void**)&hh,   g_hh);
    cudaGetSymbolAddress((void**)&xh,   g_xh);
    cudaGetSymbolAddress((void**)&qkvh, g_qkvh);
    cudaGetSymbolAddress((void**)&qkvl, g_qkvl);
    cudaGetSymbolAddress((void**)&ath,  g_ath);
    cudaGetSymbolAddress((void**)&ffh,  g_ffh);
    cudaGetSymbolAddress((void**)&wth,  g_wt_hi);
    cudaGetSymbolAddress((void**)&wtl,  g_wt_lo);
    float* part = (float*)ffh;   // free scratch at pool time

    cudaFuncSetAttribute(gemm_bf<0>, cudaFuncAttributeMaxDynamicSharedMemorySize, GEMM_SMEM);
    cudaFuncSetAttribute(gemm_bf<1>, cudaFuncAttributeMaxDynamicSharedMemorySize, GEMM_SMEM);
    cudaFuncSetAttribute(gemm_bf<2>, cudaFuncAttributeMaxDynamicSharedMemorySize, GEMM_SMEM);
    cudaFuncSetAttribute(gemm_bf<3>, cudaFuncAttributeMaxDynamicSharedMemorySize, GEMM_SMEM);
    cudaFuncSetAttribute(flash_kernel, cudaFuncAttributeMaxDynamicSharedMemorySize, FLASH_SMEM);

    // weight prep: nineteen 512x512 matrices in ONE launch + W1/W2 batched
    size_t hb = (size_t)LNUM * LSTRIDE;
    TSTab tab;
    for (int l = 0; l < LNUM; l++) {
        tab.src[l * 4 + 0] = Wq + (size_t)l * DM * DM;
        tab.src[l * 4 + 1] = Wk + (size_t)l * DM * DM;
        tab.src[l * 4 + 2] = Wv + (size_t)l * DM * DM;
        tab.src[l * 4 + 3] = Wo + (size_t)l * DM * DM;
        tab.dst[l * 4 + 0] = (long)l * LSTRIDE;
        tab.dst[l * 4 + 1] = (long)l * LSTRIDE + DM * DM;
        tab.dst[l * 4 + 2] = (long)l * LSTRIDE + 2 * DM * DM;
        tab.dst[l * 4 + 3] = (long)l * LSTRIDE + OFF_WO;
    }
    tab.src[16] = heavy_w;  tab.dst[16] = (long)hb;
    tab.src[17] = heavy_a1; tab.dst[17] = (long)hb + DM * DM;
    tab.src[18] = heavy_a2; tab.dst[18] = (long)hb + 2 * DM * DM;

    dim3 tb(32, 8);
    tsplit19_kernel<<<dim3(16, 16, 19), tb>>>(tab, wth, wtl);
    tsplit_kernel<<<dim3(FFD / 32, 16, LNUM), tb>>>(W1, wth + OFF_W1, wtl + OFF_W1, DM, FFD,
                                                    (long)DM * FFD, LSTRIDE);
    tsplit_kernel<<<dim3(16, FFD / 32, LNUM), tb>>>(W2, wth + OFF_W2, wtl + OFF_W2, FFD, DM,
                                                    (long)FFD * DM, LSTRIDE);
    bpack_kernel<<<LNUM, DM>>>(bq, bk, bv, bqkv);

    // fused embedding + layer-0 LN1
    embed_ln_kernel<<<NTOK, 128>>>(tokens, emb, x, hh, ln1_g, ln1_b);

    dim3 gQKV(3 * DM / 128, NTOK / 128);
    dim3 gD(DM / 128, NTOK / 128);
    dim3 gF(FFD / 128, NTOK / 128);
    dim3 gFA(BSZ * HN, TSEQ / 64);
    const int NOLO = 1 << 30;
    const int LNG = NTOK / 2;   // ln grid (2 rows per block)

    for (int l = 0; l < LNUM; l++) {
        const __nv_bfloat16* wb_h = wth + (size_t)l * LSTRIDE;
        const __nv_bfloat16* wb_l = wtl + (size_t)l * LSTRIDE;

        if (l > 0)
            ln_kernel<<<LNG, 256>>>(x, nullptr, hh, ln1_g + l * DM, ln1_b + l * DM);
        // lo-part written only for the K slice (cols 512..1024) — flash reads only K-lo
        gemm_bf<0><<<gQKV, 256, GEMM_SMEM>>>(hh, wb_h, wb_l, bqkv + l * 3 * DM,
                                             nullptr, nullptr, qkvh, qkvl, DM, 3 * DM,
                                             DM, 2 * DM);
        flash_kernel<<<gFA, 128, FLASH_SMEM>>>(qkvh, qkvl, ath);
        gemm_bf<1><<<gD, 256, GEMM_SMEM>>>(ath, wb_h + OFF_WO, wb_l + OFF_WO,
                                           bo + l * DM, x, x, nullptr, nullptr, DM, DM,
                                           0, NOLO);

        ln_kernel<<<LNG, 256>>>(x, nullptr, hh, ln2_g + l * DM, ln2_b + l * DM);
        gemm_bf<2><<<gF, 256, GEMM_SMEM>>>(hh, wb_h + OFF_W1, wb_l + OFF_W1,
                                           b1 + l * FFD, nullptr, nullptr, ffh, nullptr,
                                           DM, FFD, 0, NOLO);
        bool last = (l == LNUM - 1);
        // last FF2: fp32 x is never read again (heavy consumes xh) -> skip Cf
        gemm_bf<1><<<gD, 256, GEMM_SMEM>>>(ffh, wb_h + OFF_W2, wb_l + OFF_W2,
                                           b2 + l * DM, x, last ? nullptr : x,
                                           last ? xh : nullptr, nullptr, FFD, DM,
                                           0, NOLO);
    }

    // heavy: tanh(((x @ hw) @ ha1) @ ha2 + hb)
    gemm_bf<0><<<gD, 256, GEMM_SMEM>>>(xh, wth + hb, wtl + hb,
                                       nullptr, nullptr, nullptr, hh, nullptr, DM, DM, 0, NOLO);
    gemm_bf<0><<<gD, 256, GEMM_SMEM>>>(hh, wth + hb + DM * DM, wtl + hb + DM * DM,
                                       nullptr, nullptr, nullptr, qkvh, nullptr, DM, DM, 0, NOLO);
    gemm_bf<3><<<gD, 256, GEMM_SMEM>>>(qkvh, wth + hb + 2 * DM * DM, wtl + hb + 2 * DM * DM,
                                       heavy_b, nullptr, tmp, nullptr, nullptr, DM, DM, 0, NOLO);

    ln_kernel<<<LNG, 256>>>(tmp, x, nullptr, norm_g, norm_b);
    pool1_kernel<<<dim3(BSZ * 8, DM / 128), 128>>>(x, part);
    pool2_kernel<<<dim3(BSZ, DM / 128), 128>>>(part, pool);
    cls_kernel<<<BSZ * NCLS, 128>>>(pool, cls_W, cls_b, out);
    (void)in_sizes; (void)n_in; (void)out_size;
}